// round 14
// baseline (speedup 1.0000x reference)
#include <cuda_runtime.h>
#include <cstdint>

#define IN_C     16
#define OUT_C    16
#define POS_C    16
#define KOFF     8
#define TEMP     8.0f
#define TPB      128
#define WPB      4
#define WTILE    32            // edges per warp-tile
#define ASTRIDE  48            // bytes per bf16 tile row (16 bf16 + pad)

// ---------------------------------------------------------------------------
__global__ void init_out_kernel(float* __restrict__ out,
                                const float* __restrict__ bias, int total) {
    int idx = blockIdx.x * blockDim.x + threadIdx.x;
    if (idx < total) out[idx] = bias[idx & (OUT_C - 1)];
}

// ---------------------------------------------------------------------------
__device__ __forceinline__ uint32_t smem_u32(const void* p) {
    uint32_t a;
    asm("{ .reg .u64 t; cvta.to.shared.u64 t, %1; cvt.u32.u64 %0, t; }"
        : "=r"(a) : "l"(p));
    return a;
}
__device__ __forceinline__ uint32_t bf2(float h, float l) {
    uint32_t r;
    asm("cvt.rn.bf16x2.f32 %0, %1, %2;" : "=r"(r) : "f"(h), "f"(l));
    return r;
}
__device__ __forceinline__ float bf_lo(uint32_t v) { return __uint_as_float(v << 16); }
__device__ __forceinline__ float bf_hi(uint32_t v) { return __uint_as_float(v & 0xffff0000u); }
__device__ __forceinline__ float rcpf(float v) {
    float r;
    asm("rcp.approx.f32 %0, %1;" : "=f"(r) : "f"(v));
    return r;
}

#define LDSM_X4(r0, r1, r2, r3, addr)                                        \
    asm volatile("ldmatrix.sync.aligned.m8n8.x4.shared.b16 {%0,%1,%2,%3}, [%4];" \
                 : "=r"(r0), "=r"(r1), "=r"(r2), "=r"(r3) : "r"(addr))
#define LDSM_X2(r0, r1, addr)                                                \
    asm volatile("ldmatrix.sync.aligned.m8n8.x2.shared.b16 {%0,%1}, [%2];"   \
                 : "=r"(r0), "=r"(r1) : "r"(addr))

__device__ __forceinline__ void mma_bf16(float* c, const uint32_t* a,
                                         uint32_t b0, uint32_t b1) {
    asm volatile(
        "mma.sync.aligned.m16n8k16.row.col.f32.bf16.bf16.f32 "
        "{%0,%1,%2,%3}, {%4,%5,%6,%7}, {%8,%9}, {%0,%1,%2,%3};"
        : "+f"(c[0]), "+f"(c[1]), "+f"(c[2]), "+f"(c[3])
        : "r"(a[0]), "r"(a[1]), "r"(a[2]), "r"(a[3]), "r"(b0), "r"(b1));
}

__device__ __forceinline__ void cvt_hilo(float4 v, uint32_t* hw, uint32_t* lw) {
    hw[0] = bf2(v.y, v.x);
    hw[1] = bf2(v.w, v.z);
    float r0 = v.x - bf_lo(hw[0]);
    float r1 = v.y - bf_hi(hw[0]);
    float r2 = v.z - bf_lo(hw[1]);
    float r3 = v.w - bf_hi(hw[1]);
    lw[0] = bf2(r1, r0);
    lw[1] = bf2(r3, r2);
}

// ---------------------------------------------------------------------------
// Warp-autonomous 32-edge tiles; occupancy raised to 5 CTAs/SM (20 warps) by
// moving the Bl (weight-lo) fragments out of registers into a 4KB SMEM
// fragment-layout array (1 conflict-free LDS.128 per np in the Y-loop).
// Bh + O fragments stay persistent in registers; alpha stays in registers.
// ---------------------------------------------------------------------------
__global__ __launch_bounds__(TPB, 5)
void genconv_mma_kernel(const float* __restrict__ x,
                        const float* __restrict__ pos,
                        const int*   __restrict__ ei,
                        const float* __restrict__ ea,
                        const float* __restrict__ offset,
                        const float* __restrict__ weight,
                        float* __restrict__ out, int E, int nT32,
                        int nWarpsTot) {
    __shared__ __align__(16) unsigned char sAhi[WPB][WTILE * ASTRIDE];
    __shared__ __align__(16) unsigned char sAlo[WPB][WTILE * ASTRIDE];
    __shared__ __align__(16) unsigned char sDhi[WPB][WTILE * ASTRIDE];
    __shared__ __align__(16) unsigned char sDlo[WPB][WTILE * ASTRIDE];
    __shared__ __align__(16) unsigned char sBhi[128 * ASTRIDE];
    __shared__ __align__(16) unsigned char sBlo[128 * ASTRIDE];
    __shared__ __align__(16) unsigned char sOfh[8 * ASTRIDE];
    __shared__ __align__(16) unsigned char sOfl[8 * ASTRIDE];
    __shared__ __align__(16) uint4 sBlf[8][32];      // Bl fragments [np][lane]
    __shared__ __align__(16) float s_d2[WPB][WTILE];
    __shared__ __align__(16) float s_ea[WPB][WTILE];
    __shared__ __align__(16) int   s_r[WPB][WTILE];
    __shared__ __align__(16) float s_o2[KOFF];

    const int tid  = threadIdx.x;
    const int lane = tid & 31;
    const int wrp  = tid >> 5;

    const uint32_t uAhi = smem_u32(sAhi[wrp]);
    const uint32_t uAlo = smem_u32(sAlo[wrp]);
    const uint32_t uDhi = smem_u32(sDhi[wrp]);
    const uint32_t uDlo = smem_u32(sDlo[wrp]);
    const uint32_t uBhi = smem_u32(sBhi);
    const uint32_t uBlo = smem_u32(sBlo);
    const uint32_t uOfh = smem_u32(sOfh);
    const uint32_t uOfl = smem_u32(sOfl);

    // ---- init: o2 + (-2*offset) bf16 tile ----
    if (tid < KOFF) {
        float s = 0.f;
        const float* orow = offset + tid * POS_C;
#pragma unroll
        for (int p = 0; p < POS_C; p++) s += orow[p] * orow[p];
        s_o2[tid] = s;
#pragma unroll
        for (int q = 0; q < 4; q++) {
            float4 v = *reinterpret_cast<const float4*>(orow + q * 4);
            v.x *= -2.f; v.y *= -2.f; v.z *= -2.f; v.w *= -2.f;
            uint32_t hw[2], lw[2];
            cvt_hilo(v, hw, lw);
            *reinterpret_cast<uint2*>(sOfh + tid * ASTRIDE + q * 8) = make_uint2(hw[0], hw[1]);
            *reinterpret_cast<uint2*>(sOfl + tid * ASTRIDE + q * 8) = make_uint2(lw[0], lw[1]);
        }
    }

    // ---- build B tile: row n = k*16+o = tid holds W[k][o][0:16] ----
    {
        int k = tid >> 4, o = tid & 15;
        const float* wrow = weight + k * (OUT_C * IN_C) + o * IN_C;
#pragma unroll
        for (int q = 0; q < 4; q++) {
            float4 v = *reinterpret_cast<const float4*>(wrow + q * 4);
            uint32_t hw[2], lw[2];
            cvt_hilo(v, hw, lw);
            *reinterpret_cast<uint2*>(sBhi + tid * ASTRIDE + q * 8) = make_uint2(hw[0], hw[1]);
            *reinterpret_cast<uint2*>(sBlo + tid * ASTRIDE + q * 8) = make_uint2(lw[0], lw[1]);
        }
    }
    __syncthreads();

    // ---- persistent fragments: Bh (weights-hi) in regs; Bl -> SMEM frags ----
    uint32_t Bh[8][4];
#pragma unroll
    for (int np = 0; np < 8; np++) {
        uint32_t boff = (uint32_t)(np * 16 + (lane & 15)) * ASTRIDE
                      + (uint32_t)(lane >> 4) * 16;
        LDSM_X4(Bh[np][0], Bh[np][1], Bh[np][2], Bh[np][3], uBhi + boff);
        if (wrp == 0) {   // fragments identical across warps; warp 0 publishes
            uint32_t l0, l1, l2, l3;
            LDSM_X4(l0, l1, l2, l3, uBlo + boff);
            sBlf[np][lane] = make_uint4(l0, l1, l2, l3);
        }
    }
    uint32_t Oh[2], Ol[2];
    {
        uint32_t ooff = (uint32_t)(lane & 7) * ASTRIDE + ((uint32_t)(lane >> 3) & 1) * 16;
        LDSM_X2(Oh[0], Oh[1], uOfh + ooff);
        LDSM_X2(Ol[0], Ol[1], uOfl + ooff);
    }
    __syncthreads();

    // ---- tile-invariant lane constants ----
    const uint32_t frag_off0 = (uint32_t)(lane & 15) * ASTRIDE
                             + (uint32_t)(lane >> 4) * 16;           // mt=0
    const uint32_t frag_off1 = frag_off0 + 16u * ASTRIDE;            // mt=1
    const int rb      = lane >> 2;
    const int col0    = 2 * (lane & 3);
    const int np_base = lane & ~3;
    const int ebg     = lane >> 2;
    const int q       = lane & 3;

    const int gwarp = blockIdx.x * WPB + wrp;

    for (int t = gwarp; t < nT32; t += nWarpsTot) {
        // ============ gather: 4 lanes/edge, 4 passes (8 edges/pass) ========
#pragma unroll
        for (int p = 0; p < 4; p++) {
            int el = p * 8 + ebg;
            int e  = min(t * WTILE + el, E - 1);
            int r  = ei[e];
            int c  = ei[E + e];
            float4 av = *reinterpret_cast<const float4*>(pos + (size_t)c * POS_C + q * 4);
            float4 bv = *reinterpret_cast<const float4*>(pos + (size_t)r * POS_C + q * 4);
            float4 dq;
            dq.x = av.x - bv.x; dq.y = av.y - bv.y;
            dq.z = av.z - bv.z; dq.w = av.w - bv.w;

            float p2 = dq.x*dq.x + dq.y*dq.y + dq.z*dq.z + dq.w*dq.w;
            p2 += __shfl_xor_sync(0xffffffffu, p2, 1);
            p2 += __shfl_xor_sync(0xffffffffu, p2, 2);

            uint32_t hw[2], lw[2];
            cvt_hilo(dq, hw, lw);
            *reinterpret_cast<uint2*>(sDhi[wrp] + el * ASTRIDE + q * 8) = make_uint2(hw[0], hw[1]);
            *reinterpret_cast<uint2*>(sDlo[wrp] + el * ASTRIDE + q * 8) = make_uint2(lw[0], lw[1]);

            float4 xv = *reinterpret_cast<const float4*>(x + (size_t)c * IN_C + q * 4);
            cvt_hilo(xv, hw, lw);
            *reinterpret_cast<uint2*>(sAhi[wrp] + el * ASTRIDE + q * 8) = make_uint2(hw[0], hw[1]);
            *reinterpret_cast<uint2*>(sAlo[wrp] + el * ASTRIDE + q * 8) = make_uint2(lw[0], lw[1]);

            if (q == 0) {
                s_r[wrp][el]  = r;
                s_d2[wrp][el] = p2;
                s_ea[wrp][el] = ea[e];
            }
        }
        __syncwarp();

        // ============ logit GEMM: d[32x16] * (-2*off)^T[16x8] ============
        float cl[2][4];
#pragma unroll
        for (int mt = 0; mt < 2; mt++) {
            uint32_t Dh[4], Dl[4];
            uint32_t aoff = (mt == 0) ? frag_off0 : frag_off1;
            LDSM_X4(Dh[0], Dh[1], Dh[2], Dh[3], uDhi + aoff);
            LDSM_X4(Dl[0], Dl[1], Dl[2], Dl[3], uDlo + aoff);
            cl[mt][0] = cl[mt][1] = cl[mt][2] = cl[mt][3] = 0.f;
            mma_bf16(cl[mt], Dh, Oh[0], Oh[1]);
            mma_bf16(cl[mt], Dh, Ol[0], Ol[1]);
            mma_bf16(cl[mt], Dl, Oh[0], Oh[1]);
        }

        // ============ softmax in fragment layout; alpha in regs ============
        float av_[2][2][2];
        {
            float2 o2p = *reinterpret_cast<const float2*>(&s_o2[col0]);
            float lg[2][2][2], mx[2][2];
#pragma unroll
            for (int mt = 0; mt < 2; mt++) {
                float d2a = s_d2[wrp][rb + mt * 16];
                float d2b = s_d2[wrp][rb + mt * 16 + 8];
                lg[mt][0][0] = -TEMP * sqrtf(fmaxf(d2a + o2p.x + cl[mt][0], 0.f));
                lg[mt][0][1] = -TEMP * sqrtf(fmaxf(d2a + o2p.y + cl[mt][1], 0.f));
                lg[mt][1][0] = -TEMP * sqrtf(fmaxf(d2b + o2p.x + cl[mt][2], 0.f));
                lg[mt][1][1] = -TEMP * sqrtf(fmaxf(d2b + o2p.y + cl[mt][3], 0.f));
                mx[mt][0] = fmaxf(lg[mt][0][0], lg[mt][0][1]);
                mx[mt][1] = fmaxf(lg[mt][1][0], lg[mt][1][1]);
            }
#pragma unroll
            for (int mt = 0; mt < 2; mt++)
#pragma unroll
                for (int rh = 0; rh < 2; rh++) {
                    float m = mx[mt][rh];
                    m = fmaxf(m, __shfl_xor_sync(0xffffffffu, m, 1));
                    m = fmaxf(m, __shfl_xor_sync(0xffffffffu, m, 2));
                    mx[mt][rh] = m;
                }
#pragma unroll
            for (int mt = 0; mt < 2; mt++)
#pragma unroll
                for (int rh = 0; rh < 2; rh++) {
                    float e0 = __expf(lg[mt][rh][0] - mx[mt][rh]);
                    float e1 = __expf(lg[mt][rh][1] - mx[mt][rh]);
                    float s = e0 + e1;
                    s += __shfl_xor_sync(0xffffffffu, s, 1);
                    s += __shfl_xor_sync(0xffffffffu, s, 2);
                    int el = rb + mt * 16 + rh * 8;
                    int valid = (t * WTILE + el) < E;
                    float inv = valid ? (s_ea[wrp][el] * rcpf(s)) : 0.f;
                    av_[mt][rh][0] = e0 * inv;
                    av_[mt][rh][1] = e1 * inv;
                }
        }

        // ============ Y-GEMM per mt + scatter ============
#pragma unroll
        for (int mt = 0; mt < 2; mt++) {
            float aA[2][8];
#pragma unroll
            for (int np = 0; np < 8; np++) {
                aA[0][np] = __shfl_sync(0xffffffffu, av_[mt][0][np & 1],
                                        np_base | (np >> 1));
                aA[1][np] = __shfl_sync(0xffffffffu, av_[mt][1][np & 1],
                                        np_base | (np >> 1));
            }
            uint32_t Ah[4], Al[4];
            {
                uint32_t aoff = (mt == 0) ? frag_off0 : frag_off1;
                LDSM_X4(Ah[0], Ah[1], Ah[2], Ah[3], uAhi + aoff);
                LDSM_X4(Al[0], Al[1], Al[2], Al[3], uAlo + aoff);
            }
            float msg[2][2][2];
#pragma unroll
            for (int i = 0; i < 2; i++)
#pragma unroll
                for (int j = 0; j < 2; j++) { msg[i][j][0] = 0.f; msg[i][j][1] = 0.f; }

#pragma unroll
            for (int np = 0; np < 8; np++) {
                float aA0 = aA[0][np];
                float aA1 = aA[1][np];
                uint4 blf = sBlf[np][lane];   // Bl fragment, 1 LDS.128
                {
                    float c[4] = {0.f, 0.f, 0.f, 0.f};
                    mma_bf16(c, Ah, Bh[np][0], Bh[np][2]);
                    mma_bf16(c, Ah, blf.x, blf.z);
                    mma_bf16(c, Al, Bh[np][0], Bh[np][2]);
                    msg[0][0][0] = fmaf(aA0, c[0], msg[0][0][0]);
                    msg[0][0][1] = fmaf(aA0, c[1], msg[0][0][1]);
                    msg[1][0][0] = fmaf(aA1, c[2], msg[1][0][0]);
                    msg[1][0][1] = fmaf(aA1, c[3], msg[1][0][1]);
                }
                {
                    float c[4] = {0.f, 0.f, 0.f, 0.f};
                    mma_bf16(c, Ah, Bh[np][1], Bh[np][3]);
                    mma_bf16(c, Ah, blf.y, blf.w);
                    mma_bf16(c, Al, Bh[np][1], Bh[np][3]);
                    msg[0][1][0] = fmaf(aA0, c[0], msg[0][1][0]);
                    msg[0][1][1] = fmaf(aA0, c[1], msg[0][1][1]);
                    msg[1][1][0] = fmaf(aA1, c[2], msg[1][1][0]);
                    msg[1][1][1] = fmaf(aA1, c[3], msg[1][1][1]);
                }
            }
#pragma unroll
            for (int rh = 0; rh < 2; rh++) {
                int el = rb + mt * 16 + rh * 8;
                int rr = s_r[wrp][el];
                float* dst = out + (size_t)rr * OUT_C + col0;
                asm volatile("red.global.add.v2.f32 [%0], {%1, %2};"
                             :: "l"(dst), "f"(msg[rh][0][0]), "f"(msg[rh][0][1]) : "memory");
                asm volatile("red.global.add.v2.f32 [%0], {%1, %2};"
                             :: "l"(dst + 8), "f"(msg[rh][1][0]), "f"(msg[rh][1][1]) : "memory");
            }
        }
        __syncwarp();
    }
}

// ---------------------------------------------------------------------------
extern "C" void kernel_launch(void* const* d_in, const int* in_sizes, int n_in,
                              void* d_out, int out_size) {
    const float* x      = (const float*)d_in[0];
    const float* pos    = (const float*)d_in[1];
    const int*   ei     = (const int*)  d_in[2];
    const float* ea     = (const float*)d_in[3];
    const float* offset = (const float*)d_in[4];
    const float* weight = (const float*)d_in[5];
    const float* bias   = (const float*)d_in[6];
    float* out = (float*)d_out;

    int E = in_sizes[3];
    int total_out = out_size;

    int init_blocks = (total_out + 255) / 256;
    init_out_kernel<<<init_blocks, 256>>>(out, bias, total_out);

    int nT32 = (E + WTILE - 1) / WTILE;
    int blocks = 740;                       // 5 per SM, persistent
    int nWarpsTot = blocks * WPB;
    genconv_mma_kernel<<<blocks, TPB>>>(x, pos, ei, ea, offset, weight,
                                        out, E, nT32, nWarpsTot);
}

// round 15
// speedup vs baseline: 1.1951x; 1.1951x over previous
#include <cuda_runtime.h>
#include <cstdint>

#define IN_C     16
#define OUT_C    16
#define POS_C    16
#define KOFF     8
#define TEMP     8.0f
#define TPB      128
#define WPB      4
#define WTILE    32            // edges per warp-tile
#define ASTRIDE  48            // bytes per bf16 tile row (16 bf16 + pad)
#define FULLM    0xffffffffu

// ---------------------------------------------------------------------------
__global__ void init_out_kernel(float* __restrict__ out,
                                const float* __restrict__ bias, int total) {
    int idx = blockIdx.x * blockDim.x + threadIdx.x;
    if (idx < total) out[idx] = bias[idx & (OUT_C - 1)];
}

// ---------------------------------------------------------------------------
__device__ __forceinline__ uint32_t smem_u32(const void* p) {
    uint32_t a;
    asm("{ .reg .u64 t; cvta.to.shared.u64 t, %1; cvt.u32.u64 %0, t; }"
        : "=r"(a) : "l"(p));
    return a;
}
__device__ __forceinline__ uint32_t bf2(float h, float l) {
    uint32_t r;
    asm("cvt.rn.bf16x2.f32 %0, %1, %2;" : "=r"(r) : "f"(h), "f"(l));
    return r;
}
__device__ __forceinline__ float bf_lo(uint32_t v) { return __uint_as_float(v << 16); }
__device__ __forceinline__ float bf_hi(uint32_t v) { return __uint_as_float(v & 0xffff0000u); }
__device__ __forceinline__ float rcpf(float v) {
    float r;
    asm("rcp.approx.f32 %0, %1;" : "=f"(r) : "f"(v));
    return r;
}

#define LDSM_X4(r0, r1, r2, r3, addr)                                        \
    asm volatile("ldmatrix.sync.aligned.m8n8.x4.shared.b16 {%0,%1,%2,%3}, [%4];" \
                 : "=r"(r0), "=r"(r1), "=r"(r2), "=r"(r3) : "r"(addr))
#define LDSM_X2(r0, r1, addr)                                                \
    asm volatile("ldmatrix.sync.aligned.m8n8.x2.shared.b16 {%0,%1}, [%2];"   \
                 : "=r"(r0), "=r"(r1) : "r"(addr))

__device__ __forceinline__ void mma_bf16(float* c, const uint32_t* a,
                                         uint32_t b0, uint32_t b1) {
    asm volatile(
        "mma.sync.aligned.m16n8k16.row.col.f32.bf16.bf16.f32 "
        "{%0,%1,%2,%3}, {%4,%5,%6,%7}, {%8,%9}, {%0,%1,%2,%3};"
        : "+f"(c[0]), "+f"(c[1]), "+f"(c[2]), "+f"(c[3])
        : "r"(a[0]), "r"(a[1]), "r"(a[2]), "r"(a[3]), "r"(b0), "r"(b1));
}

__device__ __forceinline__ void cvt_hilo(float4 v, uint32_t* hw, uint32_t* lw) {
    hw[0] = bf2(v.y, v.x);
    hw[1] = bf2(v.w, v.z);
    float r0 = v.x - bf_lo(hw[0]);
    float r1 = v.y - bf_hi(hw[0]);
    float r2 = v.z - bf_lo(hw[1]);
    float r3 = v.w - bf_hi(hw[1]);
    lw[0] = bf2(r1, r0);
    lw[1] = bf2(r3, r2);
}

// ---------------------------------------------------------------------------
// Warp-autonomous 32-edge tiles; B + O fragments fully register-persistent
// (R13 base). New: cross-tile ei/ea prefetch (coalesced, shfl-distributed),
// d2 kept in registers (fragment-row aligned), and split MMA accumulator
// chains (depth 3 -> 2) in both the logit and Y GEMMs.
// ---------------------------------------------------------------------------
__global__ __launch_bounds__(TPB, 4)
void genconv_mma_kernel(const float* __restrict__ x,
                        const float* __restrict__ pos,
                        const int*   __restrict__ ei,
                        const float* __restrict__ ea,
                        const float* __restrict__ offset,
                        const float* __restrict__ weight,
                        float* __restrict__ out, int E, int nT32,
                        int nWarpsTot) {
    __shared__ __align__(16) unsigned char sAhi[WPB][WTILE * ASTRIDE];
    __shared__ __align__(16) unsigned char sAlo[WPB][WTILE * ASTRIDE];
    __shared__ __align__(16) unsigned char sDhi[WPB][WTILE * ASTRIDE];
    __shared__ __align__(16) unsigned char sDlo[WPB][WTILE * ASTRIDE];
    __shared__ __align__(16) unsigned char sBhi[128 * ASTRIDE];
    __shared__ __align__(16) unsigned char sBlo[128 * ASTRIDE];
    __shared__ __align__(16) unsigned char sOfh[8 * ASTRIDE];
    __shared__ __align__(16) unsigned char sOfl[8 * ASTRIDE];
    __shared__ __align__(16) float s_ea[WPB][WTILE];
    __shared__ __align__(16) int   s_r[WPB][WTILE];
    __shared__ __align__(16) float s_o2[KOFF];

    const int tid  = threadIdx.x;
    const int lane = tid & 31;
    const int wrp  = tid >> 5;

    const uint32_t uAhi = smem_u32(sAhi[wrp]);
    const uint32_t uAlo = smem_u32(sAlo[wrp]);
    const uint32_t uDhi = smem_u32(sDhi[wrp]);
    const uint32_t uDlo = smem_u32(sDlo[wrp]);
    const uint32_t uBhi = smem_u32(sBhi);
    const uint32_t uBlo = smem_u32(sBlo);
    const uint32_t uOfh = smem_u32(sOfh);
    const uint32_t uOfl = smem_u32(sOfl);

    // ---- init: o2 + (-2*offset) bf16 tile ----
    if (tid < KOFF) {
        float s = 0.f;
        const float* orow = offset + tid * POS_C;
#pragma unroll
        for (int p = 0; p < POS_C; p++) s += orow[p] * orow[p];
        s_o2[tid] = s;
#pragma unroll
        for (int q = 0; q < 4; q++) {
            float4 v = *reinterpret_cast<const float4*>(orow + q * 4);
            v.x *= -2.f; v.y *= -2.f; v.z *= -2.f; v.w *= -2.f;
            uint32_t hw[2], lw[2];
            cvt_hilo(v, hw, lw);
            *reinterpret_cast<uint2*>(sOfh + tid * ASTRIDE + q * 8) = make_uint2(hw[0], hw[1]);
            *reinterpret_cast<uint2*>(sOfl + tid * ASTRIDE + q * 8) = make_uint2(lw[0], lw[1]);
        }
    }

    // ---- build B tile: row n = k*16+o = tid holds W[k][o][0:16] ----
    {
        int k = tid >> 4, o = tid & 15;
        const float* wrow = weight + k * (OUT_C * IN_C) + o * IN_C;
#pragma unroll
        for (int q = 0; q < 4; q++) {
            float4 v = *reinterpret_cast<const float4*>(wrow + q * 4);
            uint32_t hw[2], lw[2];
            cvt_hilo(v, hw, lw);
            *reinterpret_cast<uint2*>(sBhi + tid * ASTRIDE + q * 8) = make_uint2(hw[0], hw[1]);
            *reinterpret_cast<uint2*>(sBlo + tid * ASTRIDE + q * 8) = make_uint2(lw[0], lw[1]);
        }
    }
    __syncthreads();

    // ---- persistent fragments: B (weights), O (offsets) ----
    uint32_t Bh[8][4], Bl[8][4];
#pragma unroll
    for (int np = 0; np < 8; np++) {
        uint32_t boff = (uint32_t)(np * 16 + (lane & 15)) * ASTRIDE
                      + (uint32_t)(lane >> 4) * 16;
        LDSM_X4(Bh[np][0], Bh[np][1], Bh[np][2], Bh[np][3], uBhi + boff);
        LDSM_X4(Bl[np][0], Bl[np][1], Bl[np][2], Bl[np][3], uBlo + boff);
    }
    uint32_t Oh[2], Ol[2];
    {
        uint32_t ooff = (uint32_t)(lane & 7) * ASTRIDE + ((uint32_t)(lane >> 3) & 1) * 16;
        LDSM_X2(Oh[0], Oh[1], uOfh + ooff);
        LDSM_X2(Ol[0], Ol[1], uOfl + ooff);
    }

    // ---- tile-invariant lane constants ----
    const uint32_t frag_off0 = (uint32_t)(lane & 15) * ASTRIDE
                             + (uint32_t)(lane >> 4) * 16;           // mt=0
    const uint32_t frag_off1 = frag_off0 + 16u * ASTRIDE;            // mt=1
    const int rb      = lane >> 2;         // fragment row / gather edge-in-pass
    const int col0    = 2 * (lane & 3);
    const int np_base = lane & ~3;
    const int q       = lane & 3;          // gather: 16B chunk

    const int gwarp = blockIdx.x * WPB + wrp;

    // ---- prefetch edge indices / attrs for the first tile (coalesced) ----
    int rCur, cCur;
    float eaCur;
    {
        int e0 = min(gwarp * WTILE + lane, E - 1);
        rCur  = ei[e0];
        cCur  = ei[E + e0];
        eaCur = ea[e0];
    }

    for (int t = gwarp; t < nT32; t += nWarpsTot) {
        // ---- prefetch NEXT tile's indices (hidden under this tile's body) --
        int rNxt, cNxt;
        float eaNxt;
        {
            int en = min((t + nWarpsTot) * WTILE + lane, E - 1);
            rNxt  = ei[en];
            cNxt  = ei[E + en];
            eaNxt = ea[en];
        }

        // publish this tile's r / ea once, coalesced
        s_r[wrp][lane]  = rCur;
        s_ea[wrp][lane] = eaCur;

        // ============ gather: 4 lanes/edge, 4 passes (8 edges/pass) ========
        float d2Reg[4];   // d2 of edge p*8+rb, exactly the fragment-row lane
#pragma unroll
        for (int p = 0; p < 4; p++) {
            int el = p * 8 + rb;
            int r  = __shfl_sync(FULLM, rCur, el);
            int c  = __shfl_sync(FULLM, cCur, el);
            float4 av = *reinterpret_cast<const float4*>(pos + (size_t)c * POS_C + q * 4);
            float4 bv = *reinterpret_cast<const float4*>(pos + (size_t)r * POS_C + q * 4);
            float4 dq;
            dq.x = av.x - bv.x; dq.y = av.y - bv.y;
            dq.z = av.z - bv.z; dq.w = av.w - bv.w;

            float p2 = dq.x*dq.x + dq.y*dq.y + dq.z*dq.z + dq.w*dq.w;
            p2 += __shfl_xor_sync(FULLM, p2, 1);
            p2 += __shfl_xor_sync(FULLM, p2, 2);
            d2Reg[p] = p2;

            uint32_t hw[2], lw[2];
            cvt_hilo(dq, hw, lw);
            *reinterpret_cast<uint2*>(sDhi[wrp] + el * ASTRIDE + q * 8) = make_uint2(hw[0], hw[1]);
            *reinterpret_cast<uint2*>(sDlo[wrp] + el * ASTRIDE + q * 8) = make_uint2(lw[0], lw[1]);

            float4 xv = *reinterpret_cast<const float4*>(x + (size_t)c * IN_C + q * 4);
            cvt_hilo(xv, hw, lw);
            *reinterpret_cast<uint2*>(sAhi[wrp] + el * ASTRIDE + q * 8) = make_uint2(hw[0], hw[1]);
            *reinterpret_cast<uint2*>(sAlo[wrp] + el * ASTRIDE + q * 8) = make_uint2(lw[0], lw[1]);
        }
        __syncwarp();

        // ============ logit GEMM (split accumulators, depth 2) ============
        float clA[2][4], clB[2][4];
#pragma unroll
        for (int mt = 0; mt < 2; mt++) {
            uint32_t Dh[4], Dl[4];
            uint32_t aoff = (mt == 0) ? frag_off0 : frag_off1;
            LDSM_X4(Dh[0], Dh[1], Dh[2], Dh[3], uDhi + aoff);
            LDSM_X4(Dl[0], Dl[1], Dl[2], Dl[3], uDlo + aoff);
            clA[mt][0] = clA[mt][1] = clA[mt][2] = clA[mt][3] = 0.f;
            clB[mt][0] = clB[mt][1] = clB[mt][2] = clB[mt][3] = 0.f;
            mma_bf16(clA[mt], Dh, Oh[0], Oh[1]);
            mma_bf16(clB[mt], Dh, Ol[0], Ol[1]);
            mma_bf16(clA[mt], Dl, Oh[0], Oh[1]);
        }

        // ============ softmax in fragment layout; alpha in regs ============
        float av_[2][2][2];
        {
            float2 o2p = *reinterpret_cast<const float2*>(&s_o2[col0]);
            float lg[2][2][2], mx[2][2];
#pragma unroll
            for (int mt = 0; mt < 2; mt++) {
                float d2a = d2Reg[mt * 2 + 0];
                float d2b = d2Reg[mt * 2 + 1];
                lg[mt][0][0] = -TEMP * sqrtf(fmaxf(d2a + o2p.x + clA[mt][0] + clB[mt][0], 0.f));
                lg[mt][0][1] = -TEMP * sqrtf(fmaxf(d2a + o2p.y + clA[mt][1] + clB[mt][1], 0.f));
                lg[mt][1][0] = -TEMP * sqrtf(fmaxf(d2b + o2p.x + clA[mt][2] + clB[mt][2], 0.f));
                lg[mt][1][1] = -TEMP * sqrtf(fmaxf(d2b + o2p.y + clA[mt][3] + clB[mt][3], 0.f));
                mx[mt][0] = fmaxf(lg[mt][0][0], lg[mt][0][1]);
                mx[mt][1] = fmaxf(lg[mt][1][0], lg[mt][1][1]);
            }
#pragma unroll
            for (int mt = 0; mt < 2; mt++)
#pragma unroll
                for (int rh = 0; rh < 2; rh++) {
                    float m = mx[mt][rh];
                    m = fmaxf(m, __shfl_xor_sync(FULLM, m, 1));
                    m = fmaxf(m, __shfl_xor_sync(FULLM, m, 2));
                    mx[mt][rh] = m;
                }
#pragma unroll
            for (int mt = 0; mt < 2; mt++)
#pragma unroll
                for (int rh = 0; rh < 2; rh++) {
                    float e0 = __expf(lg[mt][rh][0] - mx[mt][rh]);
                    float e1 = __expf(lg[mt][rh][1] - mx[mt][rh]);
                    float s = e0 + e1;
                    s += __shfl_xor_sync(FULLM, s, 1);
                    s += __shfl_xor_sync(FULLM, s, 2);
                    int el = rb + mt * 16 + rh * 8;
                    int valid = (t * WTILE + el) < E;
                    float inv = valid ? (s_ea[wrp][el] * rcpf(s)) : 0.f;
                    av_[mt][rh][0] = e0 * inv;
                    av_[mt][rh][1] = e1 * inv;
                }
        }

        // ============ Y-GEMM per mt (split accumulators) + scatter ========
#pragma unroll
        for (int mt = 0; mt < 2; mt++) {
            uint32_t Ah[4], Al[4];
            {
                uint32_t aoff = (mt == 0) ? frag_off0 : frag_off1;
                LDSM_X4(Ah[0], Ah[1], Ah[2], Ah[3], uAhi + aoff);
                LDSM_X4(Al[0], Al[1], Al[2], Al[3], uAlo + aoff);
            }
            float msg[2][2][2];
#pragma unroll
            for (int i = 0; i < 2; i++)
#pragma unroll
                for (int j = 0; j < 2; j++) { msg[i][j][0] = 0.f; msg[i][j][1] = 0.f; }

#pragma unroll
            for (int blk = 0; blk < 2; blk++) {
                // hoisted alpha shfls in blocks of 4 np (reg-pressure cap)
                float aA[2][4];
#pragma unroll
                for (int j = 0; j < 4; j++) {
                    int np = blk * 4 + j;
                    aA[0][j] = __shfl_sync(FULLM, av_[mt][0][np & 1],
                                           np_base | (np >> 1));
                    aA[1][j] = __shfl_sync(FULLM, av_[mt][1][np & 1],
                                           np_base | (np >> 1));
                }
#pragma unroll
                for (int j = 0; j < 4; j++) {
                    int np = blk * 4 + j;
                    float aA0 = aA[0][j];
                    float aA1 = aA[1][j];
                    {   // sub-n 0: chains cA (depth 2) + cB (depth 1)
                        float cA[4] = {0.f, 0.f, 0.f, 0.f};
                        float cB[4] = {0.f, 0.f, 0.f, 0.f};
                        mma_bf16(cA, Ah, Bh[np][0], Bh[np][2]);
                        mma_bf16(cB, Ah, Bl[np][0], Bl[np][2]);
                        mma_bf16(cA, Al, Bh[np][0], Bh[np][2]);
                        msg[0][0][0] = fmaf(aA0, cA[0], fmaf(aA0, cB[0], msg[0][0][0]));
                        msg[0][0][1] = fmaf(aA0, cA[1], fmaf(aA0, cB[1], msg[0][0][1]));
                        msg[1][0][0] = fmaf(aA1, cA[2], fmaf(aA1, cB[2], msg[1][0][0]));
                        msg[1][0][1] = fmaf(aA1, cA[3], fmaf(aA1, cB[3], msg[1][0][1]));
                    }
                    {   // sub-n 1
                        float cA[4] = {0.f, 0.f, 0.f, 0.f};
                        float cB[4] = {0.f, 0.f, 0.f, 0.f};
                        mma_bf16(cA, Ah, Bh[np][1], Bh[np][3]);
                        mma_bf16(cB, Ah, Bl[np][1], Bl[np][3]);
                        mma_bf16(cA, Al, Bh[np][1], Bh[np][3]);
                        msg[0][1][0] = fmaf(aA0, cA[0], fmaf(aA0, cB[0], msg[0][1][0]));
                        msg[0][1][1] = fmaf(aA0, cA[1], fmaf(aA0, cB[1], msg[0][1][1]));
                        msg[1][1][0] = fmaf(aA1, cA[2], fmaf(aA1, cB[2], msg[1][1][0]));
                        msg[1][1][1] = fmaf(aA1, cA[3], fmaf(aA1, cB[3], msg[1][1][1]));
                    }
                }
            }
#pragma unroll
            for (int rh = 0; rh < 2; rh++) {
                int el = rb + mt * 16 + rh * 8;
                int rr = s_r[wrp][el];
                float* dst = out + (size_t)rr * OUT_C + col0;
                asm volatile("red.global.add.v2.f32 [%0], {%1, %2};"
                             :: "l"(dst), "f"(msg[rh][0][0]), "f"(msg[rh][0][1]) : "memory");
                asm volatile("red.global.add.v2.f32 [%0], {%1, %2};"
                             :: "l"(dst + 8), "f"(msg[rh][1][0]), "f"(msg[rh][1][1]) : "memory");
            }
        }

        rCur  = rNxt;
        cCur  = cNxt;
        eaCur = eaNxt;
        __syncwarp();   // per-warp buffers safe to overwrite next iteration
    }
}

// ---------------------------------------------------------------------------
extern "C" void kernel_launch(void* const* d_in, const int* in_sizes, int n_in,
                              void* d_out, int out_size) {
    const float* x      = (const float*)d_in[0];
    const float* pos    = (const float*)d_in[1];
    const int*   ei     = (const int*)  d_in[2];
    const float* ea     = (const float*)d_in[3];
    const float* offset = (const float*)d_in[4];
    const float* weight = (const float*)d_in[5];
    const float* bias   = (const float*)d_in[6];
    float* out = (float*)d_out;

    int E = in_sizes[3];
    int total_out = out_size;

    int init_blocks = (total_out + 255) / 256;
    init_out_kernel<<<init_blocks, 256>>>(out, bias, total_out);

    int nT32 = (E + WTILE - 1) / WTILE;
    int blocks = 592;                       // 4 per SM, persistent
    int nWarpsTot = blocks * WPB;
    genconv_mma_kernel<<<blocks, TPB>>>(x, pos, ei, ea, offset, weight,
                                        out, E, nT32, nWarpsTot);
}